// round 8
// baseline (speedup 1.0000x reference)
#include <cuda_runtime.h>
#include <cuda_fp16.h>
#include <math.h>
#include <stdint.h>

// Problem constants
#define B_  2
#define L_  2048
#define D_  1024
#define H_  16
#define HD  64
#define M_  (B_ * L_)   // 4096

// ---------------------------------------------------------------------------
// Scratch (static device globals; no dynamic allocation allowed)
// ---------------------------------------------------------------------------
__device__ __half g_xh[M_ * D_];      // split of x; reused for y
__device__ __half g_xl[M_ * D_];
__device__ __half g_qh[M_ * D_];
__device__ __half g_ql[M_ * D_];
__device__ __half g_kh[M_ * D_];      // K: hi only is consumed downstream
__device__ __half g_kl[M_ * D_];
__device__ __half g_vh[M_ * D_];
__device__ __half g_vl[M_ * D_];
__device__ __half g_wh[4 * D_ * D_];  // transposed split weights
__device__ __half g_wl[4 * D_ * D_];
__device__ float2 g_rt[L_ * 32];      // (sin, cos) per (pos, pair)

// ---------------------------------------------------------------------------
// Helpers
// ---------------------------------------------------------------------------
__device__ __forceinline__ void mma16816(float* c,
                                         uint32_t a0, uint32_t a1,
                                         uint32_t a2, uint32_t a3,
                                         uint32_t b0, uint32_t b1)
{
    asm volatile(
        "mma.sync.aligned.m16n8k16.row.col.f32.f16.f16.f32 "
        "{%0,%1,%2,%3}, {%4,%5,%6,%7}, {%8,%9}, {%0,%1,%2,%3};"
        : "+f"(c[0]), "+f"(c[1]), "+f"(c[2]), "+f"(c[3])
        : "r"(a0), "r"(a1), "r"(a2), "r"(a3), "r"(b0), "r"(b1));
}

__device__ __forceinline__ void ldsm4(uint32_t& r0, uint32_t& r1,
                                      uint32_t& r2, uint32_t& r3, uint32_t a)
{
    asm volatile("ldmatrix.sync.aligned.m8n8.x4.shared.b16 {%0,%1,%2,%3}, [%4];"
                 : "=r"(r0), "=r"(r1), "=r"(r2), "=r"(r3) : "r"(a));
}

__device__ __forceinline__ void ldsm4t(uint32_t& r0, uint32_t& r1,
                                       uint32_t& r2, uint32_t& r3, uint32_t a)
{
    asm volatile("ldmatrix.sync.aligned.m8n8.x4.trans.shared.b16 {%0,%1,%2,%3}, [%4];"
                 : "=r"(r0), "=r"(r1), "=r"(r2), "=r"(r3) : "r"(a));
}

// fp16 hi/lo split of a float pair
__device__ __forceinline__ void split2(float x0, float x1,
                                       uint32_t& hi, uint32_t& lo)
{
    __half2 hp = __floats2half2_rn(x0, x1);
    float2 hf = __half22float2(hp);
    __half2 lp = __floats2half2_rn(x0 - hf.x, x1 - hf.y);
    hi = *(uint32_t*)&hp;
    lo = *(uint32_t*)&lp;
}

__device__ __forceinline__ uint32_t smem_u32(const void* p) {
    uint32_t a;
    asm("{ .reg .u64 t; cvta.to.shared.u64 t, %1; cvt.u32.u64 %0, t; }"
        : "=r"(a) : "l"(p));
    return a;
}

__device__ __forceinline__ void cpa16(uint32_t dst, const void* src) {
    asm volatile("cp.async.cg.shared.global [%0], [%1], 16;"
                 :: "r"(dst), "l"(src));
}
#define CP_COMMIT  asm volatile("cp.async.commit_group;")
#define CP_WAIT(n) asm volatile("cp.async.wait_group %0;" :: "n"(n))

// ---------------------------------------------------------------------------
// RoPE table
// ---------------------------------------------------------------------------
__global__ __launch_bounds__(256) void ropetab_kernel()
{
    int idx = blockIdx.x * blockDim.x + threadIdx.x;   // < 65536
    int pos = idx >> 5;
    int i   = idx & 31;
    float freq = exp2f(-13.287712379549449f * (float)(2 * i) * (1.0f / 64.0f));
    float s, c;
    sincosf((float)pos * freq, &s, &c);
    g_rt[idx] = make_float2(s, c);
}

// ---------------------------------------------------------------------------
// split_f32
// ---------------------------------------------------------------------------
__global__ __launch_bounds__(256) void split_f32(
    const float* __restrict__ src,
    __half* __restrict__ hi, __half* __restrict__ lo)
{
    int i = blockIdx.x * blockDim.x + threadIdx.x;
    float4 v = ((const float4*)src)[i];
    uint32_t h0, l0, h1, l1;
    split2(v.x, v.y, h0, l0);
    split2(v.z, v.w, h1, l1);
    ((uint32_t*)hi)[2 * i]     = h0;
    ((uint32_t*)hi)[2 * i + 1] = h1;
    ((uint32_t*)lo)[2 * i]     = l0;
    ((uint32_t*)lo)[2 * i + 1] = l1;
}

// ---------------------------------------------------------------------------
// splitw: transpose + split weights
// ---------------------------------------------------------------------------
__global__ __launch_bounds__(256) void splitw(
    const float* __restrict__ W0, const float* __restrict__ W1,
    const float* __restrict__ W2, const float* __restrict__ W3)
{
    __shared__ float tile[32][33];
    const float* srcs[4] = {W0, W1, W2, W3};
    const float* src = srcs[blockIdx.z];

    int x = blockIdx.x * 32 + threadIdx.x;   // n
    int y = blockIdx.y * 32 + threadIdx.y;   // k
#pragma unroll
    for (int i = 0; i < 4; ++i)
        tile[threadIdx.y + i * 8][threadIdx.x] = src[(size_t)(y + i * 8) * D_ + x];
    __syncthreads();

    uint32_t* whu = (uint32_t*)g_wh;
    uint32_t* wlu = (uint32_t*)g_wl;
    int tid2 = threadIdx.y * 32 + threadIdx.x;
#pragma unroll
    for (int p = 0; p < 2; ++p) {
        int q = tid2 + p * 256;
        int nl = q >> 4;
        int kp = q & 15;
        uint32_t hi, lo;
        split2(tile[2 * kp][nl], tile[2 * kp + 1][nl], hi, lo);
        size_t o = ((size_t)(blockIdx.z * D_ + blockIdx.x * 32 + nl) * D_
                    + blockIdx.y * 32) / 2 + kp;
        whu[o] = hi;
        wlu[o] = lo;
    }
}

// ---------------------------------------------------------------------------
// gemm_qkv: C = alpha * A @ B^T, pre-split fp16, cp.async 2-stage, ldmatrix.
// mode 0: fused QKV + RoPE + split epilogue. Q,K (sel<2): 2-pass; V: 3-pass.
// mode 1: 3-pass, f32 output.
// ---------------------------------------------------------------------------
#define PST 20                       // smem row stride in u32 (80 bytes)
#define TILE_B (128 * PST * 4)       // 10240 bytes per operand tile
#define STAGE_B (4 * TILE_B)         // 40960
#define GEMM2_SMEM (2 * STAGE_B)     // 81920

__global__ __launch_bounds__(256, 2) void gemm_qkv(
    const __half* __restrict__ Agh, const __half* __restrict__ Agl,
    const __half* __restrict__ Bgh, const __half* __restrict__ Bgl,
    uint32_t* __restrict__ Qh, uint32_t* __restrict__ Ql,
    uint32_t* __restrict__ Kh, uint32_t* __restrict__ Kl,
    uint32_t* __restrict__ Vh, uint32_t* __restrict__ Vl,
    float* __restrict__ Of32, float alpha0, int mode)
{
    extern __shared__ char smp[];
    const uint32_t sb = smem_u32(smp);

    const int tid = threadIdx.x;
    const int wid = tid >> 5;
    const int lane = tid & 31;
    const int wm = wid & 1;
    const int wn = wid >> 1;
    const int g  = lane >> 2;
    const int t  = lane & 3;
    const int m0 = blockIdx.y * 128;
    const int nb = blockIdx.x;
    const int nrow0 = nb * 128;
    const int sel = nb >> 3;
    const float alpha = (sel == 0) ? alpha0 : 1.0f;
    const int n0 = (nb & 7) * 128;
    const bool pass3 = (mode == 1) || (sel == 2);

    // ldmatrix lane offsets (bytes within a tile)
    const uint32_t aoff = (uint32_t)(((lane & 15) * PST + (lane >> 4) * 4) * 4);
    const uint32_t boff = (uint32_t)(((((lane >> 4) << 3) + (lane & 7)) * PST
                                      + ((lane >> 3) & 1) * 4) * 4);

    float acc[4][4][4];
#pragma unroll
    for (int i = 0; i < 4; ++i)
#pragma unroll
        for (int j = 0; j < 4; ++j)
#pragma unroll
            for (int r = 0; r < 4; ++r) acc[i][j][r] = 0.0f;

    const int ldrow = tid >> 2;
    const int ldcc  = tid & 3;

    auto issue = [&](int c, int s) {
        const int k0 = c * 32;
#pragma unroll
        for (int i = 0; i < 2; ++i) {
            int row = ldrow + i * 64;
            uint32_t so = (uint32_t)(s * STAGE_B + row * 80 + ldcc * 16);
            size_t ga = (size_t)(m0 + row) * D_ + k0 + ldcc * 8;
            size_t gb = (size_t)(nrow0 + row) * D_ + k0 + ldcc * 8;
            cpa16(sb + so,              Agh + ga);
            cpa16(sb + so + TILE_B,     Agl + ga);
            cpa16(sb + so + 2 * TILE_B, Bgh + gb);
            cpa16(sb + so + 3 * TILE_B, Bgl + gb);
        }
    };

    issue(0, 0);
    CP_COMMIT;

    for (int c = 0; c < D_ / 32; ++c) {
        const int s = c & 1;
        if (c + 1 < D_ / 32) {
            issue(c + 1, s ^ 1);
            CP_COMMIT;
            CP_WAIT(1);
        } else {
            CP_WAIT(0);
        }
        __syncthreads();

        const uint32_t Ab = sb + s * STAGE_B;
        const uint32_t Bb = Ab + 2 * TILE_B;

#pragma unroll
        for (int ks = 0; ks < 2; ++ks) {
            uint32_t bh[4][2], bl[4][2];
#pragma unroll
            for (int jp = 0; jp < 2; ++jp) {
                uint32_t ba = Bb + boff
                            + (uint32_t)(((wn * 32 + jp * 16) * PST + ks * 8) * 4);
                ldsm4(bh[2 * jp][0], bh[2 * jp][1],
                      bh[2 * jp + 1][0], bh[2 * jp + 1][1], ba);
                if (pass3)
                    ldsm4(bl[2 * jp][0], bl[2 * jp][1],
                          bl[2 * jp + 1][0], bl[2 * jp + 1][1], ba + TILE_B);
            }
#pragma unroll
            for (int i = 0; i < 4; ++i) {
                uint32_t aa = Ab + aoff
                            + (uint32_t)(((wm * 64 + i * 16) * PST + ks * 8) * 4);
                uint32_t ah[4], al[4];
                ldsm4(ah[0], ah[1], ah[2], ah[3], aa);
                ldsm4(al[0], al[1], al[2], al[3], aa + TILE_B);
#pragma unroll
                for (int j = 0; j < 4; ++j) {
                    mma16816(acc[i][j], ah[0], ah[1], ah[2], ah[3], bh[j][0], bh[j][1]);
                    mma16816(acc[i][j], al[0], al[1], al[2], al[3], bh[j][0], bh[j][1]);
                    if (pass3)
                        mma16816(acc[i][j], ah[0], ah[1], ah[2], ah[3], bl[j][0], bl[j][1]);
                }
            }
        }
        __syncthreads();
    }

    // ---- Epilogue
    uint32_t* Uh = (sel == 0) ? Qh : (sel == 1) ? Kh : Vh;
    uint32_t* Ul = (sel == 0) ? Ql : (sel == 1) ? Kl : Vl;

#pragma unroll
    for (int i = 0; i < 4; ++i) {
        int row = m0 + wm * 64 + i * 16 + g;
#pragma unroll
        for (int j = 0; j < 4; ++j) {
            int col = n0 + wn * 32 + j * 8 + t * 2;
            float2 o0 = make_float2(alpha * acc[i][j][0], alpha * acc[i][j][1]);
            float2 o1 = make_float2(alpha * acc[i][j][2], alpha * acc[i][j][3]);
            if (mode == 1) {
                *(float2*)(Of32 + (size_t)row * D_ + col)       = o0;
                *(float2*)(Of32 + (size_t)(row + 8) * D_ + col) = o1;
            } else {
                if (sel < 2) {   // RoPE for Q and K
                    int ii = (col >> 1) & 31;
                    float2 sc0 = g_rt[(row & (L_ - 1)) * 32 + ii];
                    float2 sc1 = g_rt[((row + 8) & (L_ - 1)) * 32 + ii];
                    o0 = make_float2(o0.x * sc0.y - o0.y * sc0.x,
                                     o0.y * sc0.y + o0.x * sc0.x);
                    o1 = make_float2(o1.x * sc1.y - o1.y * sc1.x,
                                     o1.y * sc1.y + o1.x * sc1.x);
                }
                uint32_t h0, l0, h1, l1;
                split2(o0.x, o0.y, h0, l0);
                split2(o1.x, o1.y, h1, l1);
                size_t u0 = ((size_t)row * D_ + col) >> 1;
                size_t u1 = ((size_t)(row + 8) * D_ + col) >> 1;
                Uh[u0] = h0;
                Uh[u1] = h1;
                if (sel != 1) {   // K-lo never consumed (flash QK is 2-pass)
                    Ul[u0] = l0;
                    Ul[u1] = l1;
                }
            }
        }
    }
}

// ---------------------------------------------------------------------------
// flash4: tensor-core flash attention, fp16 pre-split inputs.
// QK 2-pass (qh*kh + ql*kh; only K-hi in smem); PV 3-pass.
// Double-buffered cp.async K/V tiles; ldmatrix fragments.
// ---------------------------------------------------------------------------
#define FROW_B 144                   // 36 u32 row stride
#define FARR_B (64 * FROW_B)         // 9216 bytes per array
#define FSTAGE_B (3 * FARR_B)        // 27648 (Kh, Vh, Vl)
#define FLASH_SMEM (2 * FSTAGE_B)    // 55296

__global__ __launch_bounds__(256, 2) void flash4(
    const uint32_t* __restrict__ qh, const uint32_t* __restrict__ ql,
    const uint32_t* __restrict__ kh,
    const uint32_t* __restrict__ vh, const uint32_t* __restrict__ vl,
    uint32_t* __restrict__ yh, uint32_t* __restrict__ yl)
{
    extern __shared__ char fsm[];
    const uint32_t sb = smem_u32(fsm);

    const int tid  = threadIdx.x;
    const int wid  = tid >> 5;
    const int lane = tid & 31;
    const int g = lane >> 2;
    const int t = lane & 3;
    const int q0 = blockIdx.x * 128;
    const int h  = blockIdx.y;
    const int b  = blockIdx.z;

    // ldmatrix lane offsets (bytes within an array)
    const uint32_t koff = (uint32_t)(((((lane >> 4) << 3) + (lane & 7)) * 36
                                      + ((lane >> 3) & 1) * 4) * 4);
    const uint32_t voff = (uint32_t)(((((lane >> 3) & 1) * 8 + (lane & 7)) * 36
                                      + (lane >> 4) * 4) * 4);

    // ---- Q fragments (hi and lo; direct loads)
    uint32_t qhf[4][4], qlf[4][4];
    {
        int r0 = b * L_ + q0 + wid * 16 + g;
        const uint32_t* p  = qh + (size_t)r0 * 512 + h * 32;
        const uint32_t* pl = ql + (size_t)r0 * 512 + h * 32;
#pragma unroll
        for (int ks = 0; ks < 4; ++ks) {
            qhf[ks][0] = p[ks * 8 + t];
            qhf[ks][1] = p[8 * 512 + ks * 8 + t];
            qhf[ks][2] = p[ks * 8 + t + 4];
            qhf[ks][3] = p[8 * 512 + ks * 8 + t + 4];
            qlf[ks][0] = pl[ks * 8 + t];
            qlf[ks][1] = pl[8 * 512 + ks * 8 + t];
            qlf[ks][2] = pl[ks * 8 + t + 4];
            qlf[ks][3] = pl[8 * 512 + ks * 8 + t + 4];
        }
    }

    const int ldrow = tid >> 2;     // 0..63
    const int ldch  = tid & 3;      // chunks ldch, ldch+4

    auto issue_kv = [&](int tile, int s) {
        size_t uoff = (size_t)(b * L_ + tile * 64 + ldrow) * 512 + h * 32;
        uint32_t so = sb + (uint32_t)(s * FSTAGE_B + ldrow * FROW_B);
#pragma unroll
        for (int c2 = 0; c2 < 2; ++c2) {
            int ch = ldch + c2 * 4;
            cpa16(so + ch * 16,                kh + uoff + ch * 4);
            cpa16(so + FARR_B + ch * 16,       vh + uoff + ch * 4);
            cpa16(so + 2 * FARR_B + ch * 16,   vl + uoff + ch * 4);
        }
    };

    float acc[8][4];
#pragma unroll
    for (int j = 0; j < 8; ++j)
#pragma unroll
        for (int r = 0; r < 4; ++r) acc[j][r] = 0.0f;
    float m0r = -1e30f, m1r = -1e30f, l0r = 0.0f, l1r = 0.0f;

    issue_kv(0, 0);
    CP_COMMIT;

    for (int tile = 0; tile < L_ / 64; ++tile) {
        const int s = tile & 1;
        if (tile + 1 < L_ / 64) {
            issue_kv(tile + 1, s ^ 1);
            CP_COMMIT;
            CP_WAIT(1);
        } else {
            CP_WAIT(0);
        }
        __syncthreads();   // buffer s ready for all warps

        const uint32_t kb_ = sb + s * FSTAGE_B;        // Kh
        const uint32_t vb_ = kb_ + FARR_B;             // Vh

        // ---- S = Q K^T (2-pass) via ldmatrix
        float S[8][4];
#pragma unroll
        for (int j = 0; j < 8; ++j)
#pragma unroll
            for (int r = 0; r < 4; ++r) S[j][r] = 0.0f;
#pragma unroll
        for (int ks = 0; ks < 4; ++ks) {
#pragma unroll
            for (int jp = 0; jp < 4; ++jp) {
                uint32_t a = kb_ + koff + (uint32_t)(jp * 16 * FROW_B + ks * 32);
                uint32_t h0a, h1a, h0b, h1b;
                ldsm4(h0a, h1a, h0b, h1b, a);
                mma16816(S[2 * jp],     qhf[ks][0], qhf[ks][1], qhf[ks][2], qhf[ks][3], h0a, h1a);
                mma16816(S[2 * jp],     qlf[ks][0], qlf[ks][1], qlf[ks][2], qlf[ks][3], h0a, h1a);
                mma16816(S[2 * jp + 1], qhf[ks][0], qhf[ks][1], qhf[ks][2], qhf[ks][3], h0b, h1b);
                mma16816(S[2 * jp + 1], qlf[ks][0], qlf[ks][1], qlf[ks][2], qlf[ks][3], h0b, h1b);
            }
        }

        // ---- Online softmax
        float mx0 = -1e30f, mx1 = -1e30f;
#pragma unroll
        for (int j = 0; j < 8; ++j) {
            mx0 = fmaxf(mx0, fmaxf(S[j][0], S[j][1]));
            mx1 = fmaxf(mx1, fmaxf(S[j][2], S[j][3]));
        }
        mx0 = fmaxf(mx0, __shfl_xor_sync(0xffffffffu, mx0, 1));
        mx0 = fmaxf(mx0, __shfl_xor_sync(0xffffffffu, mx0, 2));
        mx1 = fmaxf(mx1, __shfl_xor_sync(0xffffffffu, mx1, 1));
        mx1 = fmaxf(mx1, __shfl_xor_sync(0xffffffffu, mx1, 2));

        float mn0 = fmaxf(m0r, mx0);
        float mn1 = fmaxf(m1r, mx1);
        float cr0 = __expf(m0r - mn0);
        float cr1 = __expf(m1r - mn1);
        m0r = mn0; m1r = mn1;

        float sum0 = 0.0f, sum1 = 0.0f;
#pragma unroll
        for (int j = 0; j < 8; ++j) {
            S[j][0] = __expf(S[j][0] - mn0);
            S[j][1] = __expf(S[j][1] - mn0);
            S[j][2] = __expf(S[j][2] - mn1);
            S[j][3] = __expf(S[j][3] - mn1);
            sum0 += S[j][0] + S[j][1];
            sum1 += S[j][2] + S[j][3];
        }
        sum0 += __shfl_xor_sync(0xffffffffu, sum0, 1);
        sum0 += __shfl_xor_sync(0xffffffffu, sum0, 2);
        sum1 += __shfl_xor_sync(0xffffffffu, sum1, 1);
        sum1 += __shfl_xor_sync(0xffffffffu, sum1, 2);
        l0r = l0r * cr0 + sum0;
        l1r = l1r * cr1 + sum1;
#pragma unroll
        for (int j = 0; j < 8; ++j) {
            acc[j][0] *= cr0;
            acc[j][1] *= cr0;
            acc[j][2] *= cr1;
            acc[j][3] *= cr1;
        }

        // ---- O += P V (3-pass) via ldmatrix.trans on row-major V
#pragma unroll
        for (int kb2 = 0; kb2 < 4; ++kb2) {
            uint32_t ph[4], pl[4];
            split2(S[2 * kb2][0],     S[2 * kb2][1],     ph[0], pl[0]);
            split2(S[2 * kb2][2],     S[2 * kb2][3],     ph[1], pl[1]);
            split2(S[2 * kb2 + 1][0], S[2 * kb2 + 1][1], ph[2], pl[2]);
            split2(S[2 * kb2 + 1][2], S[2 * kb2 + 1][3], ph[3], pl[3]);
#pragma unroll
            for (int jp = 0; jp < 4; ++jp) {
                uint32_t a = vb_ + voff + (uint32_t)(kb2 * 16 * FROW_B + jp * 32);
                uint32_t h0a, h1a, h0b, h1b, l0a, l1a, l0b, l1b;
                ldsm4t(h0a, h1a, h0b, h1b, a);
                ldsm4t(l0a, l1a, l0b, l1b, a + FARR_B);
                mma16816(acc[2 * jp],     ph[0], ph[1], ph[2], ph[3], h0a, h1a);
                mma16816(acc[2 * jp],     pl[0], pl[1], pl[2], pl[3], h0a, h1a);
                mma16816(acc[2 * jp],     ph[0], ph[1], ph[2], ph[3], l0a, l1a);
                mma16816(acc[2 * jp + 1], ph[0], ph[1], ph[2], ph[3], h0b, h1b);
                mma16816(acc[2 * jp + 1], pl[0], pl[1], pl[2], pl[3], h0b, h1b);
                mma16816(acc[2 * jp + 1], ph[0], ph[1], ph[2], ph[3], l0b, l1b);
            }
        }
        __syncthreads();   // all warps done with buffer s before refill
    }

    // ---- Normalize and store pre-split y
    float inv0 = 1.0f / l0r;
    float inv1 = 1.0f / l1r;
    int row0 = b * L_ + q0 + wid * 16 + g;
    size_t base0 = (size_t)row0 * 512 + h * 32;
    size_t base1 = base0 + 8 * 512;
#pragma unroll
    for (int j = 0; j < 8; ++j) {
        uint32_t h0, l0, h1, l1;
        split2(acc[j][0] * inv0, acc[j][1] * inv0, h0, l0);
        split2(acc[j][2] * inv1, acc[j][3] * inv1, h1, l1);
        yh[base0 + j * 4 + t] = h0;
        yl[base0 + j * 4 + t] = l0;
        yh[base1 + j * 4 + t] = h1;
        yl[base1 + j * 4 + t] = l1;
    }
}

// ---------------------------------------------------------------------------
// Host launcher
// ---------------------------------------------------------------------------
extern "C" void kernel_launch(void* const* d_in, const int* in_sizes, int n_in,
                              void* d_out, int out_size)
{
    const float* x  = (const float*)d_in[0];
    const float* Wq = (const float*)d_in[1];
    const float* Wk = (const float*)d_in[2];
    const float* Wv = (const float*)d_in[3];
    const float* Wo = (const float*)d_in[4];
    float* out = (float*)d_out;

    __half *xh, *xl, *wh, *wl, *qh, *ql, *kh, *kl, *vh, *vl;
    cudaGetSymbolAddress((void**)&xh, g_xh);
    cudaGetSymbolAddress((void**)&xl, g_xl);
    cudaGetSymbolAddress((void**)&wh, g_wh);
    cudaGetSymbolAddress((void**)&wl, g_wl);
    cudaGetSymbolAddress((void**)&qh, g_qh);
    cudaGetSymbolAddress((void**)&ql, g_ql);
    cudaGetSymbolAddress((void**)&kh, g_kh);
    cudaGetSymbolAddress((void**)&kl, g_kl);
    cudaGetSymbolAddress((void**)&vh, g_vh);
    cudaGetSymbolAddress((void**)&vl, g_vl);

    // 1. RoPE table, weight transpose+split, x split
    ropetab_kernel<<<(L_ * 32) / 256, 256>>>();
    splitw<<<dim3(D_ / 32, D_ / 32, 4), dim3(32, 8)>>>(Wq, Wk, Wv, Wo);
    split_f32<<<(M_ * D_ / 4) / 256, 256>>>(x, xh, xl);

    // 2. Fused QKV projection + RoPE + split epilogue (Q,K 2-pass; V 3-pass)
    cudaFuncSetAttribute(gemm_qkv,
                         cudaFuncAttributeMaxDynamicSharedMemorySize, GEMM2_SMEM);
    const float qscale = 1.0f / 32.0f;
    gemm_qkv<<<dim3(24, M_ / 128), 256, GEMM2_SMEM>>>(
        xh, xl, wh, wl,
        (uint32_t*)qh, (uint32_t*)ql, (uint32_t*)kh, (uint32_t*)kl,
        (uint32_t*)vh, (uint32_t*)vl, nullptr, qscale, 0);

    // 3. Flash attention (QK 2-pass, PV 3-pass); writes split y into xh/xl
    cudaFuncSetAttribute(flash4,
                         cudaFuncAttributeMaxDynamicSharedMemorySize, FLASH_SMEM);
    dim3 fgrid(L_ / 128, H_, B_);
    flash4<<<fgrid, 256, FLASH_SMEM>>>(
        (const uint32_t*)qh, (const uint32_t*)ql,
        (const uint32_t*)kh,
        (const uint32_t*)vh, (const uint32_t*)vl,
        (uint32_t*)xh, (uint32_t*)xl);

    // 4. Output projection (3-pass, f32 out)
    gemm_qkv<<<dim3(8, M_ / 128), 256, GEMM2_SMEM>>>(
        xh, xl, wh + 3 * D_ * D_, wl + 3 * D_ * D_,
        nullptr, nullptr, nullptr, nullptr, nullptr, nullptr,
        out, 1.0f, 1);
}

// round 9
// speedup vs baseline: 1.6244x; 1.6244x over previous
#include <cuda_runtime.h>
#include <cuda_bf16.h>
#include <math.h>
#include <stdint.h>

// Problem constants
#define B_  2
#define L_  2048
#define D_  1024
#define H_  16
#define HD  64
#define M_  (B_ * L_)   // 4096

// ---------------------------------------------------------------------------
// Scratch (static device globals; no dynamic allocation allowed)
// ---------------------------------------------------------------------------
__device__ __nv_bfloat16 g_xh[M_ * D_];      // split of x; reused for y
__device__ __nv_bfloat16 g_xl[M_ * D_];
__device__ __nv_bfloat16 g_qh[M_ * D_];
__device__ __nv_bfloat16 g_ql[M_ * D_];
__device__ __nv_bfloat16 g_kh[M_ * D_];      // K: hi only consumed downstream
__device__ __nv_bfloat16 g_vh[M_ * D_];
__device__ __nv_bfloat16 g_vl[M_ * D_];
__device__ __nv_bfloat16 g_wh[4 * D_ * D_];  // transposed split weights
__device__ __nv_bfloat16 g_wl[4 * D_ * D_];
__device__ float2 g_rt[L_ * 32];             // (sin, cos) per (pos, pair)

// ---------------------------------------------------------------------------
// Helpers
// ---------------------------------------------------------------------------
__device__ __forceinline__ void mma16816(float* c,
                                         uint32_t a0, uint32_t a1,
                                         uint32_t a2, uint32_t a3,
                                         uint32_t b0, uint32_t b1)
{
    asm volatile(
        "mma.sync.aligned.m16n8k16.row.col.f32.bf16.bf16.f32 "
        "{%0,%1,%2,%3}, {%4,%5,%6,%7}, {%8,%9}, {%0,%1,%2,%3};"
        : "+f"(c[0]), "+f"(c[1]), "+f"(c[2]), "+f"(c[3])
        : "r"(a0), "r"(a1), "r"(a2), "r"(a3), "r"(b0), "r"(b1));
}

__device__ __forceinline__ void ldsm4(uint32_t& r0, uint32_t& r1,
                                      uint32_t& r2, uint32_t& r3, uint32_t a)
{
    asm volatile("ldmatrix.sync.aligned.m8n8.x4.shared.b16 {%0,%1,%2,%3}, [%4];"
                 : "=r"(r0), "=r"(r1), "=r"(r2), "=r"(r3) : "r"(a));
}

__device__ __forceinline__ void ldsm4t(uint32_t& r0, uint32_t& r1,
                                       uint32_t& r2, uint32_t& r3, uint32_t a)
{
    asm volatile("ldmatrix.sync.aligned.m8n8.x4.trans.shared.b16 {%0,%1,%2,%3}, [%4];"
                 : "=r"(r0), "=r"(r1), "=r"(r2), "=r"(r3) : "r"(a));
}

// bf16 hi/lo split of a float pair
__device__ __forceinline__ void split2(float x0, float x1,
                                       uint32_t& hi, uint32_t& lo)
{
    __nv_bfloat162 hp = __floats2bfloat162_rn(x0, x1);
    float2 hf = __bfloat1622float2(hp);
    __nv_bfloat162 lp = __floats2bfloat162_rn(x0 - hf.x, x1 - hf.y);
    hi = *(uint32_t*)&hp;
    lo = *(uint32_t*)&lp;
}

__device__ __forceinline__ uint32_t smem_u32(const void* p) {
    uint32_t a;
    asm("{ .reg .u64 t; cvta.to.shared.u64 t, %1; cvt.u32.u64 %0, t; }"
        : "=r"(a) : "l"(p));
    return a;
}

__device__ __forceinline__ void cpa16(uint32_t dst, const void* src) {
    asm volatile("cp.async.cg.shared.global [%0], [%1], 16;"
                 :: "r"(dst), "l"(src));
}
#define CP_COMMIT  asm volatile("cp.async.commit_group;")
#define CP_WAIT(n) asm volatile("cp.async.wait_group %0;" :: "n"(n))

// ---------------------------------------------------------------------------
// RoPE table
// ---------------------------------------------------------------------------
__global__ __launch_bounds__(256) void ropetab_kernel()
{
    int idx = blockIdx.x * blockDim.x + threadIdx.x;   // < 65536
    int pos = idx >> 5;
    int i   = idx & 31;
    float freq = exp2f(-13.287712379549449f * (float)(2 * i) * (1.0f / 64.0f));
    float s, c;
    sincosf((float)pos * freq, &s, &c);
    g_rt[idx] = make_float2(s, c);
}

// ---------------------------------------------------------------------------
// split_f32
// ---------------------------------------------------------------------------
__global__ __launch_bounds__(256) void split_f32(
    const float* __restrict__ src,
    __nv_bfloat16* __restrict__ hi, __nv_bfloat16* __restrict__ lo)
{
    int i = blockIdx.x * blockDim.x + threadIdx.x;
    float4 v = ((const float4*)src)[i];
    uint32_t h0, l0, h1, l1;
    split2(v.x, v.y, h0, l0);
    split2(v.z, v.w, h1, l1);
    ((uint32_t*)hi)[2 * i]     = h0;
    ((uint32_t*)hi)[2 * i + 1] = h1;
    ((uint32_t*)lo)[2 * i]     = l0;
    ((uint32_t*)lo)[2 * i + 1] = l1;
}

// ---------------------------------------------------------------------------
// splitw: transpose + split weights
// ---------------------------------------------------------------------------
__global__ __launch_bounds__(256) void splitw(
    const float* __restrict__ W0, const float* __restrict__ W1,
    const float* __restrict__ W2, const float* __restrict__ W3)
{
    __shared__ float tile[32][33];
    const float* srcs[4] = {W0, W1, W2, W3};
    const float* src = srcs[blockIdx.z];

    int x = blockIdx.x * 32 + threadIdx.x;   // n
    int y = blockIdx.y * 32 + threadIdx.y;   // k
#pragma unroll
    for (int i = 0; i < 4; ++i)
        tile[threadIdx.y + i * 8][threadIdx.x] = src[(size_t)(y + i * 8) * D_ + x];
    __syncthreads();

    uint32_t* whu = (uint32_t*)g_wh;
    uint32_t* wlu = (uint32_t*)g_wl;
    int tid2 = threadIdx.y * 32 + threadIdx.x;
#pragma unroll
    for (int p = 0; p < 2; ++p) {
        int q = tid2 + p * 256;
        int nl = q >> 4;
        int kp = q & 15;
        uint32_t hi, lo;
        split2(tile[2 * kp][nl], tile[2 * kp + 1][nl], hi, lo);
        size_t o = ((size_t)(blockIdx.z * D_ + blockIdx.x * 32 + nl) * D_
                    + blockIdx.y * 32) / 2 + kp;
        whu[o] = hi;
        wlu[o] = lo;
    }
}

// ---------------------------------------------------------------------------
// gemm_t: C = alpha * A @ B^T, pre-split bf16, cp.async 2-stage, ldmatrix.
// Template THREE: 3-pass (vs 2-pass); MODE: 0 = split epilogue (+RoPE for
// sel<2), 1 = f32 output. nb_base offsets blockIdx.x into the fused N range.
// ---------------------------------------------------------------------------
#define PST 20                       // smem row stride in u32 (80 bytes)
#define TILE_B (128 * PST * 4)       // 10240 bytes per operand tile
#define STAGE_B (4 * TILE_B)         // 40960
#define GEMM2_SMEM (2 * STAGE_B)     // 81920

template <bool THREE, int MODE>
__global__ __launch_bounds__(256, 2) void gemm_t(
    const __nv_bfloat16* __restrict__ Agh, const __nv_bfloat16* __restrict__ Agl,
    const __nv_bfloat16* __restrict__ Bgh, const __nv_bfloat16* __restrict__ Bgl,
    uint32_t* __restrict__ Qh, uint32_t* __restrict__ Ql,
    uint32_t* __restrict__ Kh,
    uint32_t* __restrict__ Vh, uint32_t* __restrict__ Vl,
    float* __restrict__ Of32, float alpha0, int nb_base)
{
    extern __shared__ char smp[];
    const uint32_t sb = smem_u32(smp);

    const int tid = threadIdx.x;
    const int wid = tid >> 5;
    const int lane = tid & 31;
    const int wm = wid & 1;
    const int wn = wid >> 1;
    const int g  = lane >> 2;
    const int t  = lane & 3;
    const int m0 = blockIdx.y * 128;
    const int nb = nb_base + blockIdx.x;
    const int nrow0 = nb * 128;
    const int sel = nb >> 3;
    const float alpha = (sel == 0) ? alpha0 : 1.0f;
    const int n0 = (nb & 7) * 128;

    // ldmatrix lane offsets (bytes within a tile)
    const uint32_t aoff = (uint32_t)(((lane & 15) * PST + (lane >> 4) * 4) * 4);
    const uint32_t boff = (uint32_t)(((((lane >> 4) << 3) + (lane & 7)) * PST
                                      + ((lane >> 3) & 1) * 4) * 4);

    float acc[4][4][4];
#pragma unroll
    for (int i = 0; i < 4; ++i)
#pragma unroll
        for (int j = 0; j < 4; ++j)
#pragma unroll
            for (int r = 0; r < 4; ++r) acc[i][j][r] = 0.0f;

    const int ldrow = tid >> 2;
    const int ldcc  = tid & 3;

    auto issue = [&](int c, int s) {
        const int k0 = c * 32;
#pragma unroll
        for (int i = 0; i < 2; ++i) {
            int row = ldrow + i * 64;
            uint32_t so = (uint32_t)(s * STAGE_B + row * 80 + ldcc * 16);
            size_t ga = (size_t)(m0 + row) * D_ + k0 + ldcc * 8;
            size_t gb = (size_t)(nrow0 + row) * D_ + k0 + ldcc * 8;
            cpa16(sb + so,              Agh + ga);
            cpa16(sb + so + TILE_B,     Agl + ga);
            cpa16(sb + so + 2 * TILE_B, Bgh + gb);
            if (THREE)
                cpa16(sb + so + 3 * TILE_B, Bgl + gb);
        }
    };

    issue(0, 0);
    CP_COMMIT;

    for (int c = 0; c < D_ / 32; ++c) {
        const int s = c & 1;
        if (c + 1 < D_ / 32) {
            issue(c + 1, s ^ 1);
            CP_COMMIT;
            CP_WAIT(1);
        } else {
            CP_WAIT(0);
        }
        __syncthreads();

        const uint32_t Ab = sb + s * STAGE_B;
        const uint32_t Bb = Ab + 2 * TILE_B;

#pragma unroll
        for (int ks = 0; ks < 2; ++ks) {
            uint32_t bh[4][2], bl[4][2];
#pragma unroll
            for (int jp = 0; jp < 2; ++jp) {
                uint32_t ba = Bb + boff
                            + (uint32_t)(((wn * 32 + jp * 16) * PST + ks * 8) * 4);
                ldsm4(bh[2 * jp][0], bh[2 * jp][1],
                      bh[2 * jp + 1][0], bh[2 * jp + 1][1], ba);
                if (THREE)
                    ldsm4(bl[2 * jp][0], bl[2 * jp][1],
                          bl[2 * jp + 1][0], bl[2 * jp + 1][1], ba + TILE_B);
            }
#pragma unroll
            for (int i = 0; i < 4; ++i) {
                uint32_t aa = Ab + aoff
                            + (uint32_t)(((wm * 64 + i * 16) * PST + ks * 8) * 4);
                uint32_t ah[4], al[4];
                ldsm4(ah[0], ah[1], ah[2], ah[3], aa);
                ldsm4(al[0], al[1], al[2], al[3], aa + TILE_B);
#pragma unroll
                for (int j = 0; j < 4; ++j) {
                    mma16816(acc[i][j], ah[0], ah[1], ah[2], ah[3], bh[j][0], bh[j][1]);
                    mma16816(acc[i][j], al[0], al[1], al[2], al[3], bh[j][0], bh[j][1]);
                    if (THREE)
                        mma16816(acc[i][j], ah[0], ah[1], ah[2], ah[3], bl[j][0], bl[j][1]);
                }
            }
        }
        __syncthreads();
    }

    // ---- Epilogue
    uint32_t* Uh = (sel == 0) ? Qh : (sel == 1) ? Kh : Vh;
    uint32_t* Ul = (sel == 0) ? Ql : Vl;   // sel==1 never stores lo

#pragma unroll
    for (int i = 0; i < 4; ++i) {
        int row = m0 + wm * 64 + i * 16 + g;
#pragma unroll
        for (int j = 0; j < 4; ++j) {
            int col = n0 + wn * 32 + j * 8 + t * 2;
            float2 o0 = make_float2(alpha * acc[i][j][0], alpha * acc[i][j][1]);
            float2 o1 = make_float2(alpha * acc[i][j][2], alpha * acc[i][j][3]);
            if (MODE == 1) {
                *(float2*)(Of32 + (size_t)row * D_ + col)       = o0;
                *(float2*)(Of32 + (size_t)(row + 8) * D_ + col) = o1;
            } else {
                if (sel < 2) {   // RoPE for Q and K
                    int ii = (col >> 1) & 31;
                    float2 sc0 = g_rt[(row & (L_ - 1)) * 32 + ii];
                    float2 sc1 = g_rt[((row + 8) & (L_ - 1)) * 32 + ii];
                    o0 = make_float2(o0.x * sc0.y - o0.y * sc0.x,
                                     o0.y * sc0.y + o0.x * sc0.x);
                    o1 = make_float2(o1.x * sc1.y - o1.y * sc1.x,
                                     o1.y * sc1.y + o1.x * sc1.x);
                }
                uint32_t h0, l0, h1, l1;
                split2(o0.x, o0.y, h0, l0);
                split2(o1.x, o1.y, h1, l1);
                size_t u0 = ((size_t)row * D_ + col) >> 1;
                size_t u1 = ((size_t)(row + 8) * D_ + col) >> 1;
                Uh[u0] = h0;
                Uh[u1] = h1;
                if (sel != 1) {   // K-lo never consumed (flash QK is 2-pass)
                    Ul[u0] = l0;
                    Ul[u1] = l1;
                }
            }
        }
    }
}

// ---------------------------------------------------------------------------
// flash5: bf16 tensor-core flash attention, pre-split inputs.
// QK 2-pass (qh*kh + ql*kh; only K-hi in smem); PV 3-pass.
// Double-buffered cp.async K/V tiles; ldmatrix fragments.
// ---------------------------------------------------------------------------
#define FROW_B 144                   // 36 u32 row stride
#define FARR_B (64 * FROW_B)         // 9216 bytes per array
#define FSTAGE_B (3 * FARR_B)        // 27648 (Kh, Vh, Vl)
#define FLASH_SMEM (2 * FSTAGE_B)    // 55296

__global__ __launch_bounds__(256, 2) void flash5(
    const uint32_t* __restrict__ qh, const uint32_t* __restrict__ ql,
    const uint32_t* __restrict__ kh,
    const uint32_t* __restrict__ vh, const uint32_t* __restrict__ vl,
    uint32_t* __restrict__ yh, uint32_t* __restrict__ yl)
{
    extern __shared__ char fsm[];
    const uint32_t sb = smem_u32(fsm);

    const int tid  = threadIdx.x;
    const int wid  = tid >> 5;
    const int lane = tid & 31;
    const int g = lane >> 2;
    const int t = lane & 3;
    const int q0 = blockIdx.x * 128;
    const int h  = blockIdx.y;
    const int b  = blockIdx.z;

    // ldmatrix lane offsets (bytes within an array)
    const uint32_t koff = (uint32_t)(((((lane >> 4) << 3) + (lane & 7)) * 36
                                      + ((lane >> 3) & 1) * 4) * 4);
    const uint32_t voff = (uint32_t)(((((lane >> 3) & 1) * 8 + (lane & 7)) * 36
                                      + (lane >> 4) * 4) * 4);

    // ---- Q fragments (hi and lo; direct loads)
    uint32_t qhf[4][4], qlf[4][4];
    {
        int r0 = b * L_ + q0 + wid * 16 + g;
        const uint32_t* p  = qh + (size_t)r0 * 512 + h * 32;
        const uint32_t* pl = ql + (size_t)r0 * 512 + h * 32;
#pragma unroll
        for (int ks = 0; ks < 4; ++ks) {
            qhf[ks][0] = p[ks * 8 + t];
            qhf[ks][1] = p[8 * 512 + ks * 8 + t];
            qhf[ks][2] = p[ks * 8 + t + 4];
            qhf[ks][3] = p[8 * 512 + ks * 8 + t + 4];
            qlf[ks][0] = pl[ks * 8 + t];
            qlf[ks][1] = pl[8 * 512 + ks * 8 + t];
            qlf[ks][2] = pl[ks * 8 + t + 4];
            qlf[ks][3] = pl[8 * 512 + ks * 8 + t + 4];
        }
    }

    const int ldrow = tid >> 2;     // 0..63
    const int ldch  = tid & 3;      // chunks ldch, ldch+4

    auto issue_kv = [&](int tile, int s) {
        size_t uoff = (size_t)(b * L_ + tile * 64 + ldrow) * 512 + h * 32;
        uint32_t so = sb + (uint32_t)(s * FSTAGE_B + ldrow * FROW_B);
#pragma unroll
        for (int c2 = 0; c2 < 2; ++c2) {
            int ch = ldch + c2 * 4;
            cpa16(so + ch * 16,                kh + uoff + ch * 4);
            cpa16(so + FARR_B + ch * 16,       vh + uoff + ch * 4);
            cpa16(so + 2 * FARR_B + ch * 16,   vl + uoff + ch * 4);
        }
    };

    float acc[8][4];
#pragma unroll
    for (int j = 0; j < 8; ++j)
#pragma unroll
        for (int r = 0; r < 4; ++r) acc[j][r] = 0.0f;
    float m0r = -1e30f, m1r = -1e30f, l0r = 0.0f, l1r = 0.0f;

    issue_kv(0, 0);
    CP_COMMIT;

    for (int tile = 0; tile < L_ / 64; ++tile) {
        const int s = tile & 1;
        if (tile + 1 < L_ / 64) {
            issue_kv(tile + 1, s ^ 1);
            CP_COMMIT;
            CP_WAIT(1);
        } else {
            CP_WAIT(0);
        }
        __syncthreads();   // buffer s ready for all warps

        const uint32_t kb_ = sb + s * FSTAGE_B;        // Kh
        const uint32_t vb_ = kb_ + FARR_B;             // Vh

        // ---- S = Q K^T (2-pass) via ldmatrix
        float S[8][4];
#pragma unroll
        for (int j = 0; j < 8; ++j)
#pragma unroll
            for (int r = 0; r < 4; ++r) S[j][r] = 0.0f;
#pragma unroll
        for (int ks = 0; ks < 4; ++ks) {
#pragma unroll
            for (int jp = 0; jp < 4; ++jp) {
                uint32_t a = kb_ + koff + (uint32_t)(jp * 16 * FROW_B + ks * 32);
                uint32_t h0a, h1a, h0b, h1b;
                ldsm4(h0a, h1a, h0b, h1b, a);
                mma16816(S[2 * jp],     qhf[ks][0], qhf[ks][1], qhf[ks][2], qhf[ks][3], h0a, h1a);
                mma16816(S[2 * jp],     qlf[ks][0], qlf[ks][1], qlf[ks][2], qlf[ks][3], h0a, h1a);
                mma16816(S[2 * jp + 1], qhf[ks][0], qhf[ks][1], qhf[ks][2], qhf[ks][3], h0b, h1b);
                mma16816(S[2 * jp + 1], qlf[ks][0], qlf[ks][1], qlf[ks][2], qlf[ks][3], h0b, h1b);
            }
        }

        // ---- Online softmax
        float mx0 = -1e30f, mx1 = -1e30f;
#pragma unroll
        for (int j = 0; j < 8; ++j) {
            mx0 = fmaxf(mx0, fmaxf(S[j][0], S[j][1]));
            mx1 = fmaxf(mx1, fmaxf(S[j][2], S[j][3]));
        }
        mx0 = fmaxf(mx0, __shfl_xor_sync(0xffffffffu, mx0, 1));
        mx0 = fmaxf(mx0, __shfl_xor_sync(0xffffffffu, mx0, 2));
        mx1 = fmaxf(mx1, __shfl_xor_sync(0xffffffffu, mx1, 1));
        mx1 = fmaxf(mx1, __shfl_xor_sync(0xffffffffu, mx1, 2));

        float mn0 = fmaxf(m0r, mx0);
        float mn1 = fmaxf(m1r, mx1);
        float cr0 = __expf(m0r - mn0);
        float cr1 = __expf(m1r - mn1);
        m0r = mn0; m1r = mn1;

        float sum0 = 0.0f, sum1 = 0.0f;
#pragma unroll
        for (int j = 0; j < 8; ++j) {
            S[j][0] = __expf(S[j][0] - mn0);
            S[j][1] = __expf(S[j][1] - mn0);
            S[j][2] = __expf(S[j][2] - mn1);
            S[j][3] = __expf(S[j][3] - mn1);
            sum0 += S[j][0] + S[j][1];
            sum1 += S[j][2] + S[j][3];
        }
        sum0 += __shfl_xor_sync(0xffffffffu, sum0, 1);
        sum0 += __shfl_xor_sync(0xffffffffu, sum0, 2);
        sum1 += __shfl_xor_sync(0xffffffffu, sum1, 1);
        sum1 += __shfl_xor_sync(0xffffffffu, sum1, 2);
        l0r = l0r * cr0 + sum0;
        l1r = l1r * cr1 + sum1;
#pragma unroll
        for (int j = 0; j < 8; ++j) {
            acc[j][0] *= cr0;
            acc[j][1] *= cr0;
            acc[j][2] *= cr1;
            acc[j][3] *= cr1;
        }

        // ---- O += P V (3-pass) via ldmatrix.trans on row-major V
#pragma unroll
        for (int kb2 = 0; kb2 < 4; ++kb2) {
            uint32_t ph[4], pl[4];
            split2(S[2 * kb2][0],     S[2 * kb2][1],     ph[0], pl[0]);
            split2(S[2 * kb2][2],     S[2 * kb2][3],     ph[1], pl[1]);
            split2(S[2 * kb2 + 1][0], S[2 * kb2 + 1][1], ph[2], pl[2]);
            split2(S[2 * kb2 + 1][2], S[2 * kb2 + 1][3], ph[3], pl[3]);
#pragma unroll
            for (int jp = 0; jp < 4; ++jp) {
                uint32_t a = vb_ + voff + (uint32_t)(kb2 * 16 * FROW_B + jp * 32);
                uint32_t h0a, h1a, h0b, h1b, l0a, l1a, l0b, l1b;
                ldsm4t(h0a, h1a, h0b, h1b, a);
                ldsm4t(l0a, l1a, l0b, l1b, a + FARR_B);
                mma16816(acc[2 * jp],     ph[0], ph[1], ph[2], ph[3], h0a, h1a);
                mma16816(acc[2 * jp],     pl[0], pl[1], pl[2], pl[3], h0a, h1a);
                mma16816(acc[2 * jp],     ph[0], ph[1], ph[2], ph[3], l0a, l1a);
                mma16816(acc[2 * jp + 1], ph[0], ph[1], ph[2], ph[3], h0b, h1b);
                mma16816(acc[2 * jp + 1], pl[0], pl[1], pl[2], pl[3], h0b, h1b);
                mma16816(acc[2 * jp + 1], ph[0], ph[1], ph[2], ph[3], l0b, l1b);
            }
        }
        __syncthreads();   // all warps done with buffer s before refill
    }

    // ---- Normalize and store pre-split y
    float inv0 = 1.0f / l0r;
    float inv1 = 1.0f / l1r;
    int row0 = b * L_ + q0 + wid * 16 + g;
    size_t base0 = (size_t)row0 * 512 + h * 32;
    size_t base1 = base0 + 8 * 512;
#pragma unroll
    for (int j = 0; j < 8; ++j) {
        uint32_t h0, l0, h1, l1;
        split2(acc[j][0] * inv0, acc[j][1] * inv0, h0, l0);
        split2(acc[j][2] * inv1, acc[j][3] * inv1, h1, l1);
        yh[base0 + j * 4 + t] = h0;
        yl[base0 + j * 4 + t] = l0;
        yh[base1 + j * 4 + t] = h1;
        yl[base1 + j * 4 + t] = l1;
    }
}

// ---------------------------------------------------------------------------
// Host launcher
// ---------------------------------------------------------------------------
extern "C" void kernel_launch(void* const* d_in, const int* in_sizes, int n_in,
                              void* d_out, int out_size)
{
    const float* x  = (const float*)d_in[0];
    const float* Wq = (const float*)d_in[1];
    const float* Wk = (const float*)d_in[2];
    const float* Wv = (const float*)d_in[3];
    const float* Wo = (const float*)d_in[4];
    float* out = (float*)d_out;

    __nv_bfloat16 *xh, *xl, *wh, *wl, *qh, *ql, *kh, *vh, *vl;
    cudaGetSymbolAddress((void**)&xh, g_xh);
    cudaGetSymbolAddress((void**)&xl, g_xl);
    cudaGetSymbolAddress((void**)&wh, g_wh);
    cudaGetSymbolAddress((void**)&wl, g_wl);
    cudaGetSymbolAddress((void**)&qh, g_qh);
    cudaGetSymbolAddress((void**)&ql, g_ql);
    cudaGetSymbolAddress((void**)&kh, g_kh);
    cudaGetSymbolAddress((void**)&vh, g_vh);
    cudaGetSymbolAddress((void**)&vl, g_vl);

    // 1. RoPE table, weight transpose+split, x split
    ropetab_kernel<<<(L_ * 32) / 256, 256>>>();
    splitw<<<dim3(D_ / 32, D_ / 32, 4), dim3(32, 8)>>>(Wq, Wk, Wv, Wo);
    split_f32<<<(M_ * D_ / 4) / 256, 256>>>(x, xh, xl);

    // 2. Projections: Q,K (2-pass, RoPE+split epilogue), V (3-pass, split)
    cudaFuncSetAttribute(gemm_t<false, 0>,
                         cudaFuncAttributeMaxDynamicSharedMemorySize, GEMM2_SMEM);
    cudaFuncSetAttribute(gemm_t<true, 0>,
                         cudaFuncAttributeMaxDynamicSharedMemorySize, GEMM2_SMEM);
    cudaFuncSetAttribute(gemm_t<true, 1>,
                         cudaFuncAttributeMaxDynamicSharedMemorySize, GEMM2_SMEM);
    const float qscale = 1.0f / 32.0f;
    gemm_t<false, 0><<<dim3(16, M_ / 128), 256, GEMM2_SMEM>>>(
        xh, xl, wh, wl,
        (uint32_t*)qh, (uint32_t*)ql, (uint32_t*)kh,
        (uint32_t*)vh, (uint32_t*)vl, nullptr, qscale, 0);
    gemm_t<true, 0><<<dim3(8, M_ / 128), 256, GEMM2_SMEM>>>(
        xh, xl, wh, wl,
        (uint32_t*)qh, (uint32_t*)ql, (uint32_t*)kh,
        (uint32_t*)vh, (uint32_t*)vl, nullptr, qscale, 16);

    // 3. Flash attention (QK 2-pass, PV 3-pass); writes split y into xh/xl
    cudaFuncSetAttribute(flash5,
                         cudaFuncAttributeMaxDynamicSharedMemorySize, FLASH_SMEM);
    dim3 fgrid(L_ / 128, H_, B_);
    flash5<<<fgrid, 256, FLASH_SMEM>>>(
        (const uint32_t*)qh, (const uint32_t*)ql,
        (const uint32_t*)kh,
        (const uint32_t*)vh, (const uint32_t*)vl,
        (uint32_t*)xh, (uint32_t*)xl);

    // 4. Output projection (3-pass, f32 out)
    gemm_t<true, 1><<<dim3(8, M_ / 128), 256, GEMM2_SMEM>>>(
        xh, xl, wh + 3 * D_ * D_, wl + 3 * D_ * D_,
        nullptr, nullptr, nullptr, nullptr, nullptr,
        out, 1.0f, 0);
}

// round 12
// speedup vs baseline: 1.7430x; 1.0731x over previous
#include <cuda_runtime.h>
#include <cuda_bf16.h>
#include <math.h>
#include <stdint.h>

// Problem constants
#define B_  2
#define L_  2048
#define D_  1024
#define H_  16
#define HD  64
#define M_  (B_ * L_)   // 4096

// ---------------------------------------------------------------------------
// Scratch (static device globals; no dynamic allocation allowed)
// ---------------------------------------------------------------------------
__device__ float g_xr[M_ * D_];              // x rounded to tf32
__device__ float g_qf[M_ * D_];              // q (tf32-rounded); reused for y
__device__ float g_kf[M_ * D_];              // k (tf32-rounded)
__device__ __nv_bfloat16 g_vh[M_ * D_];      // v bf16 hi
__device__ __nv_bfloat16 g_vl[M_ * D_];      // v bf16 lo
__device__ float g_wt[4 * D_ * D_];          // transposed weights, tf32-rounded
__device__ float2 g_rt[L_ * 32];             // (sin, cos) per (pos, pair)

// ---------------------------------------------------------------------------
// Helpers
// ---------------------------------------------------------------------------
__device__ __forceinline__ void mma_bf16(float* c,
                                         uint32_t a0, uint32_t a1,
                                         uint32_t a2, uint32_t a3,
                                         uint32_t b0, uint32_t b1)
{
    asm volatile(
        "mma.sync.aligned.m16n8k16.row.col.f32.bf16.bf16.f32 "
        "{%0,%1,%2,%3}, {%4,%5,%6,%7}, {%8,%9}, {%0,%1,%2,%3};"
        : "+f"(c[0]), "+f"(c[1]), "+f"(c[2]), "+f"(c[3])
        : "r"(a0), "r"(a1), "r"(a2), "r"(a3), "r"(b0), "r"(b1));
}

__device__ __forceinline__ void mma_tf32(float* c,
                                         uint32_t a0, uint32_t a1,
                                         uint32_t a2, uint32_t a3,
                                         uint32_t b0, uint32_t b1)
{
    asm volatile(
        "mma.sync.aligned.m16n8k8.row.col.f32.tf32.tf32.f32 "
        "{%0,%1,%2,%3}, {%4,%5,%6,%7}, {%8,%9}, {%0,%1,%2,%3};"
        : "+f"(c[0]), "+f"(c[1]), "+f"(c[2]), "+f"(c[3])
        : "r"(a0), "r"(a1), "r"(a2), "r"(a3), "r"(b0), "r"(b1));
}

__device__ __forceinline__ void ldsm4(uint32_t& r0, uint32_t& r1,
                                      uint32_t& r2, uint32_t& r3, uint32_t a)
{
    asm volatile("ldmatrix.sync.aligned.m8n8.x4.shared.b16 {%0,%1,%2,%3}, [%4];"
                 : "=r"(r0), "=r"(r1), "=r"(r2), "=r"(r3) : "r"(a));
}

__device__ __forceinline__ void ldsm4t(uint32_t& r0, uint32_t& r1,
                                       uint32_t& r2, uint32_t& r3, uint32_t a)
{
    asm volatile("ldmatrix.sync.aligned.m8n8.x4.trans.shared.b16 {%0,%1,%2,%3}, [%4];"
                 : "=r"(r0), "=r"(r1), "=r"(r2), "=r"(r3) : "r"(a));
}

__device__ __forceinline__ uint32_t f2tf32(float x) {
    uint32_t u;
    asm("cvt.rna.tf32.f32 %0, %1;" : "=r"(u) : "f"(x));
    return u;
}

// bf16 hi/lo split of a float pair
__device__ __forceinline__ void split2(float x0, float x1,
                                       uint32_t& hi, uint32_t& lo)
{
    __nv_bfloat162 hp = __floats2bfloat162_rn(x0, x1);
    float2 hf = __bfloat1622float2(hp);
    __nv_bfloat162 lp = __floats2bfloat162_rn(x0 - hf.x, x1 - hf.y);
    hi = *(uint32_t*)&hp;
    lo = *(uint32_t*)&lp;
}

__device__ __forceinline__ uint32_t smem_u32(const void* p) {
    uint32_t a;
    asm("{ .reg .u64 t; cvta.to.shared.u64 t, %1; cvt.u32.u64 %0, t; }"
        : "=r"(a) : "l"(p));
    return a;
}

__device__ __forceinline__ void cpa16(uint32_t dst, const void* src) {
    asm volatile("cp.async.cg.shared.global [%0], [%1], 16;"
                 :: "r"(dst), "l"(src));
}
#define CP_COMMIT  asm volatile("cp.async.commit_group;")
#define CP_WAIT(n) asm volatile("cp.async.wait_group %0;" :: "n"(n))

// ---------------------------------------------------------------------------
// RoPE table
// ---------------------------------------------------------------------------
__global__ __launch_bounds__(256) void ropetab_kernel()
{
    int idx = blockIdx.x * blockDim.x + threadIdx.x;   // < 65536
    int pos = idx >> 5;
    int i   = idx & 31;
    float freq = exp2f(-13.287712379549449f * (float)(2 * i) * (1.0f / 64.0f));
    float s, c;
    sincosf((float)pos * freq, &s, &c);
    g_rt[idx] = make_float2(s, c);
}

// ---------------------------------------------------------------------------
// round_tf32: elementwise rna tf32 rounding (f32 -> f32)
// ---------------------------------------------------------------------------
__global__ __launch_bounds__(256) void round_tf32(
    const float* __restrict__ src, float* __restrict__ dst)
{
    int i = blockIdx.x * blockDim.x + threadIdx.x;
    float4 v = ((const float4*)src)[i];
    float4 o = make_float4(__uint_as_float(f2tf32(v.x)),
                           __uint_as_float(f2tf32(v.y)),
                           __uint_as_float(f2tf32(v.z)),
                           __uint_as_float(f2tf32(v.w)));
    ((float4*)dst)[i] = o;
}

// ---------------------------------------------------------------------------
// transpose_f32: g_wt[z][n][k] = tf32_round(W_z[k][n])
// ---------------------------------------------------------------------------
__global__ __launch_bounds__(256) void transpose_f32(
    const float* __restrict__ W0, const float* __restrict__ W1,
    const float* __restrict__ W2, const float* __restrict__ W3)
{
    __shared__ float tile[32][33];
    const float* srcs[4] = {W0, W1, W2, W3};
    const float* src = srcs[blockIdx.z];
    float* dst = g_wt + (size_t)blockIdx.z * D_ * D_;

    int x = blockIdx.x * 32 + threadIdx.x;
    int y = blockIdx.y * 32 + threadIdx.y;
#pragma unroll
    for (int i = 0; i < 4; ++i)
        tile[threadIdx.y + i * 8][threadIdx.x] = src[(size_t)(y + i * 8) * D_ + x];
    __syncthreads();
    x = blockIdx.y * 32 + threadIdx.x;
    y = blockIdx.x * 32 + threadIdx.y;
#pragma unroll
    for (int i = 0; i < 4; ++i)
        dst[(size_t)(y + i * 8) * D_ + x] =
            __uint_as_float(f2tf32(tile[threadIdx.x][threadIdx.y + i * 8]));
}

// ---------------------------------------------------------------------------
// gemm_tf32: C = alpha * A @ B^T, single-pass tf32 (m16n8k8); A,B exact tf32.
// EPI 0: QKV epilogue (Q/K: RoPE + tf32-round, f32; V: bf16 hi/lo split).
// EPI 1: plain f32 to Of32.
// CTA 128x128, K-chunk 32, 2-stage cp.async, ldmatrix-on-f32 fragments.
// ---------------------------------------------------------------------------
#define GST 36                        // smem row stride in f32 (144 B)
#define GTILE_B (128 * GST * 4)       // 18432 bytes per operand tile
#define GSTAGE_B (2 * GTILE_B)        // 36864
#define GEMM3_SMEM (2 * GSTAGE_B)     // 73728

template <int EPI>
__global__ __launch_bounds__(256, 2) void gemm_tf32(
    const float* __restrict__ A, const float* __restrict__ Bg,
    float* __restrict__ Qf, float* __restrict__ Kf,
    uint32_t* __restrict__ Vh, uint32_t* __restrict__ Vl,
    float* __restrict__ Of32, float alpha0)
{
    extern __shared__ char smp[];
    const uint32_t sb = smem_u32(smp);

    const int tid = threadIdx.x;
    const int wid = tid >> 5;
    const int lane = tid & 31;
    const int wm = wid & 1;
    const int wn = wid >> 1;
    const int g  = lane >> 2;
    const int t  = lane & 3;
    const int m0 = blockIdx.y * 128;
    const int nb = blockIdx.x;
    const int nrow0 = nb * 128;
    const int sel = nb >> 3;
    const int n0 = (nb & 7) * 128;

    // ldmatrix lane offsets (f32 units within a tile)
    const uint32_t aoff = (uint32_t)((lane & 15) * GST + (lane >> 4) * 4);
    const uint32_t boff = (uint32_t)(((lane & 7) + ((lane & 16) ? 8 : 0)) * GST
                                     + ((lane & 8) ? 4 : 0));

    float acc[4][4][4];
#pragma unroll
    for (int i = 0; i < 4; ++i)
#pragma unroll
        for (int j = 0; j < 4; ++j)
#pragma unroll
            for (int r = 0; r < 4; ++r) acc[i][j][r] = 0.0f;

    const int ldrow = tid >> 3;          // 0..31 (x4 -> 128 rows)
    const int ldc   = tid & 7;           // 16B chunk within 128B row

    auto issue = [&](int c, int s) {
        const int k0 = c * 32;
#pragma unroll
        for (int i = 0; i < 4; ++i) {
            int row = ldrow + i * 32;
            uint32_t so = (uint32_t)(s * GSTAGE_B + row * (GST * 4) + ldc * 16);
            cpa16(sb + so,           A  + (size_t)(m0 + row) * D_ + k0 + ldc * 4);
            cpa16(sb + so + GTILE_B, Bg + (size_t)(nrow0 + row) * D_ + k0 + ldc * 4);
        }
    };

    issue(0, 0);
    CP_COMMIT;

    for (int c = 0; c < D_ / 32; ++c) {
        const int s = c & 1;
        if (c + 1 < D_ / 32) {
            issue(c + 1, s ^ 1);
            CP_COMMIT;
            CP_WAIT(1);
        } else {
            CP_WAIT(0);
        }
        __syncthreads();

        const uint32_t Ab = sb + s * GSTAGE_B;
        const uint32_t Bb = Ab + GTILE_B;

#pragma unroll
        for (int k8 = 0; k8 < 4; ++k8) {
            uint32_t bf[4][2];
#pragma unroll
            for (int jp = 0; jp < 2; ++jp) {
                uint32_t ba = Bb + (boff + (uint32_t)((wn * 32 + jp * 16) * GST
                                                     + k8 * 8)) * 4;
                ldsm4(bf[2 * jp][0], bf[2 * jp][1],
                      bf[2 * jp + 1][0], bf[2 * jp + 1][1], ba);
            }
#pragma unroll
            for (int i = 0; i < 4; ++i) {
                uint32_t aa = Ab + (aoff + (uint32_t)((wm * 64 + i * 16) * GST
                                                     + k8 * 8)) * 4;
                uint32_t af[4];
                ldsm4(af[0], af[1], af[2], af[3], aa);
#pragma unroll
                for (int j = 0; j < 4; ++j)
                    mma_tf32(acc[i][j], af[0], af[1], af[2], af[3],
                             bf[j][0], bf[j][1]);
            }
        }
        __syncthreads();
    }

    // ---- Epilogue
    const float alpha = (EPI == 0 && sel == 0) ? alpha0 : 1.0f;
#pragma unroll
    for (int i = 0; i < 4; ++i) {
        int row = m0 + wm * 64 + i * 16 + g;
#pragma unroll
        for (int j = 0; j < 4; ++j) {
            int col = n0 + wn * 32 + j * 8 + t * 2;
            float2 o0 = make_float2(alpha * acc[i][j][0], alpha * acc[i][j][1]);
            float2 o1 = make_float2(alpha * acc[i][j][2], alpha * acc[i][j][3]);
            if (EPI == 1) {
                *(float2*)(Of32 + (size_t)row * D_ + col)       = o0;
                *(float2*)(Of32 + (size_t)(row + 8) * D_ + col) = o1;
            } else if (sel < 2) {
                // RoPE, rna-round to tf32, store f32
                int ii = (col >> 1) & 31;
                float2 sc0 = g_rt[(row & (L_ - 1)) * 32 + ii];
                float2 sc1 = g_rt[((row + 8) & (L_ - 1)) * 32 + ii];
                float r00 = o0.x * sc0.y - o0.y * sc0.x;
                float r01 = o0.y * sc0.y + o0.x * sc0.x;
                float r10 = o1.x * sc1.y - o1.y * sc1.x;
                float r11 = o1.y * sc1.y + o1.x * sc1.x;
                float* Uo = (sel == 0) ? Qf : Kf;
                *(float2*)(Uo + (size_t)row * D_ + col) =
                    make_float2(__uint_as_float(f2tf32(r00)),
                                __uint_as_float(f2tf32(r01)));
                *(float2*)(Uo + (size_t)(row + 8) * D_ + col) =
                    make_float2(__uint_as_float(f2tf32(r10)),
                                __uint_as_float(f2tf32(r11)));
            } else {
                // V: bf16 hi/lo split
                uint32_t h0, l0, h1, l1;
                split2(o0.x, o0.y, h0, l0);
                split2(o1.x, o1.y, h1, l1);
                size_t u0 = ((size_t)row * D_ + col) >> 1;
                size_t u1 = ((size_t)(row + 8) * D_ + col) >> 1;
                Vh[u0] = h0; Vl[u0] = l0;
                Vh[u1] = h1; Vl[u1] = l1;
            }
        }
    }
}

// ---------------------------------------------------------------------------
// flash7: QK single-pass tf32 (q,k exact tf32); softmax f32;
// PV 3-pass bf16 (P hi/lo x V hi/lo, drop pl*vl). Double-buffered cp.async.
// y written tf32-rounded f32 (feeds the tf32 Wo GEMM bias-free).
// ---------------------------------------------------------------------------
#define KST 68                        // K smem row stride, f32 (272 B)
#define KARR_B (64 * KST * 4)         // 17408 bytes
#define VROW 36                       // V smem row stride, u32 (144 B)
#define VARR_B (64 * VROW * 4)        // 9216 bytes
#define FSTG_B (KARR_B + 2 * VARR_B)  // 35840 per stage
#define FLASH_SMEM (2 * FSTG_B)       // 71680

__global__ __launch_bounds__(256, 2) void flash7(
    const float* __restrict__ qf, const float* __restrict__ kf,
    const uint32_t* __restrict__ vh, const uint32_t* __restrict__ vl,
    float* __restrict__ y)
{
    extern __shared__ char fsm[];
    const uint32_t sb = smem_u32(fsm);

    const int tid  = threadIdx.x;
    const int wid  = tid >> 5;
    const int lane = tid & 31;
    const int g = lane >> 2;
    const int t = lane & 3;
    const int q0 = blockIdx.x * 128;
    const int h  = blockIdx.y;
    const int b  = blockIdx.z;

    // ldmatrix lane offsets
    const uint32_t koff = (uint32_t)(((lane & 7) + ((lane & 16) ? 8 : 0)) * KST
                                     + ((lane & 8) ? 4 : 0));          // f32 units
    const uint32_t voff = (uint32_t)(((((lane >> 3) & 1) * 8 + (lane & 7)) * VROW
                                      + (lane >> 4) * 4) * 4);         // bytes

    // ---- Q fragments: tf32 a-frags, direct f32 loads
    uint32_t qa[8][4];
    {
        int r0 = b * L_ + q0 + wid * 16 + g;
        const uint32_t* p = (const uint32_t*)qf + (size_t)r0 * D_ + h * HD;
#pragma unroll
        for (int c = 0; c < 8; ++c) {
            qa[c][0] = p[c * 8 + t];
            qa[c][1] = p[8 * D_ + c * 8 + t];
            qa[c][2] = p[c * 8 + t + 4];
            qa[c][3] = p[8 * D_ + c * 8 + t + 4];
        }
    }

    const int ldrow = tid >> 2;     // 0..63
    const int ldch  = tid & 3;

    auto issue_kv = [&](int tile, int s) {
        uint32_t so = sb + (uint32_t)(s * FSTG_B);
        size_t krow = (size_t)(b * L_ + tile * 64 + ldrow);
        const float* kp = kf + krow * D_ + h * HD;
        const uint32_t* vph = vh + krow * (D_ / 2) + h * (HD / 2);
        const uint32_t* vpl = vl + krow * (D_ / 2) + h * (HD / 2);
#pragma unroll
        for (int c4 = 0; c4 < 4; ++c4) {   // K: 16 chunks of 16B per row
            int ch = ldch + c4 * 4;
            cpa16(so + ldrow * (KST * 4) + ch * 16, kp + ch * 4);
        }
#pragma unroll
        for (int c2 = 0; c2 < 2; ++c2) {   // Vh, Vl: 8 chunks each per row
            int ch = ldch + c2 * 4;
            cpa16(so + KARR_B + ldrow * (VROW * 4) + ch * 16,          vph + ch * 4);
            cpa16(so + KARR_B + VARR_B + ldrow * (VROW * 4) + ch * 16, vpl + ch * 4);
        }
    };

    float acc[8][4];
#pragma unroll
    for (int j = 0; j < 8; ++j)
#pragma unroll
        for (int r = 0; r < 4; ++r) acc[j][r] = 0.0f;
    float m0r = -1e30f, m1r = -1e30f, l0r = 0.0f, l1r = 0.0f;

    issue_kv(0, 0);
    CP_COMMIT;

    for (int tile = 0; tile < L_ / 64; ++tile) {
        const int s = tile & 1;
        if (tile + 1 < L_ / 64) {
            issue_kv(tile + 1, s ^ 1);
            CP_COMMIT;
            CP_WAIT(1);
        } else {
            CP_WAIT(0);
        }
        __syncthreads();

        const uint32_t kb_ = sb + s * FSTG_B;
        const uint32_t vb_ = kb_ + KARR_B;

        // ---- S = Q K^T, single-pass tf32 (8 n-atoms x 8 k8)
        float S[8][4];
#pragma unroll
        for (int j = 0; j < 8; ++j)
#pragma unroll
            for (int r = 0; r < 4; ++r) S[j][r] = 0.0f;
#pragma unroll
        for (int c = 0; c < 8; ++c) {
#pragma unroll
            for (int jp = 0; jp < 4; ++jp) {
                uint32_t a = kb_ + (koff + (uint32_t)(jp * 16 * KST + c * 8)) * 4;
                uint32_t b0a, b1a, b0b, b1b;
                ldsm4(b0a, b1a, b0b, b1b, a);
                mma_tf32(S[2 * jp],     qa[c][0], qa[c][1], qa[c][2], qa[c][3], b0a, b1a);
                mma_tf32(S[2 * jp + 1], qa[c][0], qa[c][1], qa[c][2], qa[c][3], b0b, b1b);
            }
        }

        // ---- Online softmax
        float mx0 = -1e30f, mx1 = -1e30f;
#pragma unroll
        for (int j = 0; j < 8; ++j) {
            mx0 = fmaxf(mx0, fmaxf(S[j][0], S[j][1]));
            mx1 = fmaxf(mx1, fmaxf(S[j][2], S[j][3]));
        }
        mx0 = fmaxf(mx0, __shfl_xor_sync(0xffffffffu, mx0, 1));
        mx0 = fmaxf(mx0, __shfl_xor_sync(0xffffffffu, mx0, 2));
        mx1 = fmaxf(mx1, __shfl_xor_sync(0xffffffffu, mx1, 1));
        mx1 = fmaxf(mx1, __shfl_xor_sync(0xffffffffu, mx1, 2));

        float mn0 = fmaxf(m0r, mx0);
        float mn1 = fmaxf(m1r, mx1);
        float cr0 = __expf(m0r - mn0);
        float cr1 = __expf(m1r - mn1);
        m0r = mn0; m1r = mn1;

        float sum0 = 0.0f, sum1 = 0.0f;
#pragma unroll
        for (int j = 0; j < 8; ++j) {
            S[j][0] = __expf(S[j][0] - mn0);
            S[j][1] = __expf(S[j][1] - mn0);
            S[j][2] = __expf(S[j][2] - mn1);
            S[j][3] = __expf(S[j][3] - mn1);
            sum0 += S[j][0] + S[j][1];
            sum1 += S[j][2] + S[j][3];
        }
        sum0 += __shfl_xor_sync(0xffffffffu, sum0, 1);
        sum0 += __shfl_xor_sync(0xffffffffu, sum0, 2);
        sum1 += __shfl_xor_sync(0xffffffffu, sum1, 1);
        sum1 += __shfl_xor_sync(0xffffffffu, sum1, 2);
        l0r = l0r * cr0 + sum0;
        l1r = l1r * cr1 + sum1;
#pragma unroll
        for (int j = 0; j < 8; ++j) {
            acc[j][0] *= cr0;
            acc[j][1] *= cr0;
            acc[j][2] *= cr1;
            acc[j][3] *= cr1;
        }

        // ---- O += P V (3-pass bf16: ph*vh + pl*vh + ph*vl)
#pragma unroll
        for (int kb2 = 0; kb2 < 4; ++kb2) {
            uint32_t ph[4], pl[4];
            split2(S[2 * kb2][0],     S[2 * kb2][1],     ph[0], pl[0]);
            split2(S[2 * kb2][2],     S[2 * kb2][3],     ph[1], pl[1]);
            split2(S[2 * kb2 + 1][0], S[2 * kb2 + 1][1], ph[2], pl[2]);
            split2(S[2 * kb2 + 1][2], S[2 * kb2 + 1][3], ph[3], pl[3]);
#pragma unroll
            for (int jp = 0; jp < 4; ++jp) {
                uint32_t a = vb_ + voff + (uint32_t)(kb2 * 16 * (VROW * 4) + jp * 32);
                uint32_t h0a, h1a, h0b, h1b, l0a, l1a, l0b, l1b;
                ldsm4t(h0a, h1a, h0b, h1b, a);
                ldsm4t(l0a, l1a, l0b, l1b, a + VARR_B);
                mma_bf16(acc[2 * jp],     ph[0], ph[1], ph[2], ph[3], h0a, h1a);
                mma_bf16(acc[2 * jp],     pl[0], pl[1], pl[2], pl[3], h0a, h1a);
                mma_bf16(acc[2 * jp],     ph[0], ph[1], ph[2], ph[3], l0a, l1a);
                mma_bf16(acc[2 * jp + 1], ph[0], ph[1], ph[2], ph[3], h0b, h1b);
                mma_bf16(acc[2 * jp + 1], pl[0], pl[1], pl[2], pl[3], h0b, h1b);
                mma_bf16(acc[2 * jp + 1], ph[0], ph[1], ph[2], ph[3], l0b, l1b);
            }
        }
        __syncthreads();
    }

    // ---- Normalize and store y (tf32-rounded f32 — exact operand for Wo)
    float inv0 = 1.0f / l0r;
    float inv1 = 1.0f / l1r;
    int row0 = b * L_ + q0 + wid * 16 + g;
    float* y0 = y + (size_t)row0 * D_ + h * HD;
    float* y1 = y0 + 8 * D_;
#pragma unroll
    for (int j = 0; j < 8; ++j) {
        *(float2*)(y0 + j * 8 + 2 * t) =
            make_float2(__uint_as_float(f2tf32(acc[j][0] * inv0)),
                        __uint_as_float(f2tf32(acc[j][1] * inv0)));
        *(float2*)(y1 + j * 8 + 2 * t) =
            make_float2(__uint_as_float(f2tf32(acc[j][2] * inv1)),
                        __uint_as_float(f2tf32(acc[j][3] * inv1)));
    }
}

// ---------------------------------------------------------------------------
// Host launcher
// ---------------------------------------------------------------------------
extern "C" void kernel_launch(void* const* d_in, const int* in_sizes, int n_in,
                              void* d_out, int out_size)
{
    const float* x  = (const float*)d_in[0];
    const float* Wq = (const float*)d_in[1];
    const float* Wk = (const float*)d_in[2];
    const float* Wv = (const float*)d_in[3];
    const float* Wo = (const float*)d_in[4];
    float* out = (float*)d_out;

    float *xr, *qf, *kf, *wt;
    __nv_bfloat16 *vh, *vl;
    cudaGetSymbolAddress((void**)&xr, g_xr);
    cudaGetSymbolAddress((void**)&qf, g_qf);
    cudaGetSymbolAddress((void**)&kf, g_kf);
    cudaGetSymbolAddress((void**)&vh, g_vh);
    cudaGetSymbolAddress((void**)&vl, g_vl);
    cudaGetSymbolAddress((void**)&wt, g_wt);

    // 1. RoPE table, weight transpose (rna tf32), x rna-rounding
    ropetab_kernel<<<(L_ * 32) / 256, 256>>>();
    transpose_f32<<<dim3(D_ / 32, D_ / 32, 4), dim3(32, 8)>>>(Wq, Wk, Wv, Wo);
    round_tf32<<<(M_ * D_ / 4) / 256, 256>>>(x, xr);

    // 2. Fused QKV projection (single-pass tf32, all operands exact tf32)
    cudaFuncSetAttribute(gemm_tf32<0>,
                         cudaFuncAttributeMaxDynamicSharedMemorySize, GEMM3_SMEM);
    cudaFuncSetAttribute(gemm_tf32<1>,
                         cudaFuncAttributeMaxDynamicSharedMemorySize, GEMM3_SMEM);
    const float qscale = 1.0f / 32.0f;
    gemm_tf32<0><<<dim3(24, M_ / 128), 256, GEMM3_SMEM>>>(
        xr, wt, qf, kf, (uint32_t*)vh, (uint32_t*)vl, nullptr, qscale);

    // 3. Flash attention (QK tf32 1-pass, PV bf16 3-pass); y into qf
    cudaFuncSetAttribute(flash7,
                         cudaFuncAttributeMaxDynamicSharedMemorySize, FLASH_SMEM);
    dim3 fgrid(L_ / 128, H_, B_);
    flash7<<<fgrid, 256, FLASH_SMEM>>>(qf, kf, (const uint32_t*)vh,
                                       (const uint32_t*)vl, qf);

    // 4. Output projection (single-pass tf32, f32 out)
    gemm_tf32<1><<<dim3(8, M_ / 128), 256, GEMM3_SMEM>>>(
        qf, wt + 3 * (size_t)D_ * D_, nullptr, nullptr, nullptr, nullptr,
        out, 1.0f);
}